// round 6
// baseline (speedup 1.0000x reference)
#include <cuda_runtime.h>
#include <math.h>

// Problem constants
#define HID   1024
#define NH    16
#define HD    64
#define MROWS 16384           // B*S = 2*8192
#define OUT_ELEMS (MROWS * HID)        // 16777216
#define M_ELEMS   (NH * HD * HD)       // 65536
#define Z_ELEMS   (NH * HD)            // 1024
#define NCHUNK 32

// Scratch (no cudaMalloc allowed -> device globals)
__device__ float g_q[MROWS * HID];    // q (then scaled to q/den in place)
__device__ float g_k[MROWS * HID];
__device__ float g_v[MROWS * HID];
__device__ float g_W2[HID * HID];     // blockdiag(M) @ Wo
__device__ float g_Mpart[NCHUNK * NH * HD * HD];   // split-S partials
__device__ float g_zpart[NCHUNK * Z_ELEMS];

// ---------------------------------------------------------------------------
// Kernel 1: W2[h*64+d, n] = sum_e M[h,d,e] * Wo[h*64+e, n]
// ---------------------------------------------------------------------------
__global__ void build_w2_kernel(const float* __restrict__ Mm,
                                const float* __restrict__ Wo) {
    __shared__ float Ms[64][64];
    __shared__ float Ws[64][64];
    const int h  = blockIdx.y;
    const int nb = blockIdx.x * 64;
    const int tid = threadIdx.x;

    for (int i = tid; i < 4096; i += 256)
        Ms[i >> 6][i & 63] = Mm[h * 4096 + i];
    for (int i = tid; i < 4096; i += 256)
        Ws[i >> 6][i & 63] = Wo[(size_t)(h * 64 + (i >> 6)) * HID + nb + (i & 63)];
    __syncthreads();

    const int nn = tid & 63;
    const int dg = tid >> 6;   // 0..3
    for (int d = dg; d < 64; d += 4) {
        float s = 0.f;
        #pragma unroll 16
        for (int e = 0; e < 64; e++) s += Ms[d][e] * Ws[e][nn];
        g_W2[(size_t)(h * 64 + d) * HID + nb + nn] = s;
    }
}

// ---------------------------------------------------------------------------
// Kernel 2: fused QKV GEMM. C = X @ W + b for W in {Wq,Wk,Wv}.
// Inner accumulation is strictly k-ascending, single accumulator, FFMA —
// matching the reference's (Eigen) fp32 gemm rounding order so q can
// bit-match. Bias added once at the end (as in ref).
// ---------------------------------------------------------------------------
#define BM 128
#define BN 128
#define BKD 8
#define TM 8
#define TN 8

__global__ __launch_bounds__(256, 2)
void gemm_qkv_kernel(const float* __restrict__ X,
                     const float* __restrict__ Wq, const float* __restrict__ Bq,
                     const float* __restrict__ Wk, const float* __restrict__ Bk,
                     const float* __restrict__ Wv, const float* __restrict__ Bv) {
    __shared__ float As[BKD][BM];
    __shared__ float Bs[BKD][BN];

    const int bm    = blockIdx.x * BM;
    const int nt    = blockIdx.y;
    const int which = nt >> 3;            // 0=q 1=k 2=v
    const int bn    = (nt & 7) * BN;      // column within [0,1024)

    const float* W    = (which == 0) ? Wq : (which == 1) ? Wk : Wv;
    const float* Bias = (which == 0) ? Bq : (which == 1) ? Bk : Bv;
    float*       Out  = (which == 0) ? g_q : (which == 1) ? g_k : g_v;

    const int tid = threadIdx.x;
    const int tx  = tid & 15;             // n-group
    const int ty  = tid >> 4;             // m-group

    const int arow  = tid >> 1;
    const int akcol = (tid & 1) * 4;
    const int bkrow = tid >> 5;
    const int bncol = (tid & 31) * 4;

    float acc[TM][TN];
    #pragma unroll
    for (int i = 0; i < TM; i++)
        #pragma unroll
        for (int j = 0; j < TN; j++) acc[i][j] = 0.f;

    const float* Aptr = X + (size_t)(bm + arow) * HID + akcol;
    const float* Wptr = W + (size_t)bkrow * HID + bn + bncol;

    for (int k0 = 0; k0 < HID; k0 += BKD) {
        float4 av = *(const float4*)(Aptr + k0);
        As[akcol + 0][arow] = av.x;
        As[akcol + 1][arow] = av.y;
        As[akcol + 2][arow] = av.z;
        As[akcol + 3][arow] = av.w;
        *(float4*)&Bs[bkrow][bncol] = *(const float4*)(Wptr + (size_t)k0 * HID);
        __syncthreads();

        #pragma unroll
        for (int kk = 0; kk < BKD; kk++) {
            float4 a0 = *(const float4*)&As[kk][ty * TM];
            float4 a1 = *(const float4*)&As[kk][ty * TM + 4];
            float4 b0 = *(const float4*)&Bs[kk][tx * TN];
            float4 b1 = *(const float4*)&Bs[kk][tx * TN + 4];
            float a[TM] = {a0.x, a0.y, a0.z, a0.w, a1.x, a1.y, a1.z, a1.w};
            float b[TN] = {b0.x, b0.y, b0.z, b0.w, b1.x, b1.y, b1.z, b1.w};
            #pragma unroll
            for (int i = 0; i < TM; i++)
                #pragma unroll
                for (int j = 0; j < TN; j++)
                    acc[i][j] = fmaf(a[i], b[j], acc[i][j]);
        }
        __syncthreads();
    }

    float bias[TN];
    #pragma unroll
    for (int j = 0; j < TN; j++) bias[j] = Bias[bn + tx * TN + j];
    #pragma unroll
    for (int i = 0; i < TM; i++)
        #pragma unroll
        for (int j = 0; j < TN; j++) acc[i][j] += bias[j];

    #pragma unroll
    for (int i = 0; i < TM; i++) {
        float* o = Out + (size_t)(bm + ty * TM + i) * HID + bn + tx * TN;
        *(float4*)(o)     = make_float4(acc[i][0], acc[i][1], acc[i][2], acc[i][3]);
        *(float4*)(o + 4) = make_float4(acc[i][4], acc[i][5], acc[i][6], acc[i][7]);
    }
}

// ---------------------------------------------------------------------------
// Kernel 3: den + scale. For each (row, head): den = |sum_d q[d]*z[d]| + eps
// with a STRICT sequential d=0..63 fmaf chain (matches reference reduction
// order), then q <- q * (1/den) in place.
// grid: (MROWS/64, NH), 256 threads. Tile [64 rows x 64 cols] in smem.
// ---------------------------------------------------------------------------
__global__ __launch_bounds__(256, 4)
void den_scale_kernel(const float* __restrict__ Z) {
    __shared__ float tile[64][65];
    __shared__ float zsh[64];
    __shared__ float inv[64];

    const int h   = blockIdx.y;
    const int r0  = blockIdx.x * 64;
    const int tid = threadIdx.x;
    const size_t base = (size_t)r0 * HID + h * 64;

    if (tid < 64) zsh[tid] = Z[h * 64 + tid];

    #pragma unroll
    for (int t = 0; t < 4; t++) {
        int idx = tid + t * 256;          // 0..1023 float4 slots
        int r   = idx >> 4;
        int c4  = (idx & 15) * 4;
        float4 v = *(const float4*)(g_q + base + (size_t)r * HID + c4);
        tile[r][c4 + 0] = v.x;
        tile[r][c4 + 1] = v.y;
        tile[r][c4 + 2] = v.z;
        tile[r][c4 + 3] = v.w;
    }
    __syncthreads();

    if (tid < 64) {
        float s = 0.f;
        // strict sequential ascending-d fmaf chain (do NOT reassociate)
        for (int d = 0; d < 64; d++)
            s = fmaf(tile[tid][d], zsh[d], s);
        inv[tid] = 1.f / (fabsf(s) + 1e-6f);
    }
    __syncthreads();

    #pragma unroll
    for (int t = 0; t < 4; t++) {
        int idx = tid + t * 256;
        int r   = idx >> 4;
        int c4  = (idx & 15) * 4;
        float iv = inv[r];
        float4 v;
        v.x = tile[r][c4 + 0] * iv;
        v.y = tile[r][c4 + 1] * iv;
        v.z = tile[r][c4 + 2] * iv;
        v.w = tile[r][c4 + 3] * iv;
        *(float4*)(g_q + base + (size_t)r * HID + c4) = v;
    }
}

// ---------------------------------------------------------------------------
// Kernel 4: out = (q/den) @ W2   [16384,1024] x [1024,1024]
// ---------------------------------------------------------------------------
__global__ __launch_bounds__(256, 2)
void gemm_out_kernel(float* __restrict__ Out) {
    __shared__ float As[BKD][BM];
    __shared__ float Bs[BKD][BN];

    const int bm = blockIdx.x * BM;
    const int bn = blockIdx.y * BN;

    const int tid = threadIdx.x;
    const int tx  = tid & 15;
    const int ty  = tid >> 4;

    const int arow  = tid >> 1;
    const int akcol = (tid & 1) * 4;
    const int bkrow = tid >> 5;
    const int bncol = (tid & 31) * 4;

    float acc[TM][TN];
    #pragma unroll
    for (int i = 0; i < TM; i++)
        #pragma unroll
        for (int j = 0; j < TN; j++) acc[i][j] = 0.f;

    const float* Aptr = g_q  + (size_t)(bm + arow) * HID + akcol;
    const float* Wptr = g_W2 + (size_t)bkrow * HID + bn + bncol;

    for (int k0 = 0; k0 < HID; k0 += BKD) {
        float4 av = *(const float4*)(Aptr + k0);
        As[akcol + 0][arow] = av.x;
        As[akcol + 1][arow] = av.y;
        As[akcol + 2][arow] = av.z;
        As[akcol + 3][arow] = av.w;
        *(float4*)&Bs[bkrow][bncol] = *(const float4*)(Wptr + (size_t)k0 * HID);
        __syncthreads();

        #pragma unroll
        for (int kk = 0; kk < BKD; kk++) {
            float4 a0 = *(const float4*)&As[kk][ty * TM];
            float4 a1 = *(const float4*)&As[kk][ty * TM + 4];
            float4 b0 = *(const float4*)&Bs[kk][tx * TN];
            float4 b1 = *(const float4*)&Bs[kk][tx * TN + 4];
            float a[TM] = {a0.x, a0.y, a0.z, a0.w, a1.x, a1.y, a1.z, a1.w};
            float b[TN] = {b0.x, b0.y, b0.z, b0.w, b1.x, b1.y, b1.z, b1.w};
            #pragma unroll
            for (int i = 0; i < TM; i++)
                #pragma unroll
                for (int j = 0; j < TN; j++)
                    acc[i][j] = fmaf(a[i], b[j], acc[i][j]);
        }
        __syncthreads();
    }

    #pragma unroll
    for (int i = 0; i < TM; i++) {
        float* o = Out + (size_t)(bm + ty * TM + i) * HID + bn + tx * TN;
        *(float4*)(o)     = make_float4(acc[i][0], acc[i][1], acc[i][2], acc[i][3]);
        *(float4*)(o + 4) = make_float4(acc[i][4], acc[i][5], acc[i][6], acc[i][7]);
    }
}

// ---------------------------------------------------------------------------
// Kernel 5: split-S partials of sum_s k (x) v and sum_s k per head.
// Deterministic: partials go to g_Mpart/g_zpart (no atomics).
// grid: (NCHUNK, NH), 256 threads, 64x64 tile, 4x4 per thread.
// ---------------------------------------------------------------------------
#define TS 16

__global__ __launch_bounds__(256, 4)
void update_state_kernel() {
    __shared__ float ks[TS][64];
    __shared__ float vs[TS][64];

    const int h      = blockIdx.y;
    const int chunk  = blockIdx.x;
    const int rows   = MROWS / NCHUNK;            // 512
    const int s_base = chunk * rows;

    const int tid = threadIdx.x;
    const int tx  = tid & 15;                     // e-group (4 cols)
    const int ty  = tid >> 4;                     // d-group (4 rows)

    const int s_l = tid >> 4;
    const int c4  = (tid & 15) * 4;

    float acc[4][4];
    #pragma unroll
    for (int i = 0; i < 4; i++)
        #pragma unroll
        for (int j = 0; j < 4; j++) acc[i][j] = 0.f;
    float zacc[4] = {0.f, 0.f, 0.f, 0.f};

    const size_t colbase = (size_t)h * 64 + c4;

    for (int s0 = s_base; s0 < s_base + rows; s0 += TS) {
        *(float4*)&ks[s_l][c4] = *(const float4*)(g_k + (size_t)(s0 + s_l) * HID + colbase);
        *(float4*)&vs[s_l][c4] = *(const float4*)(g_v + (size_t)(s0 + s_l) * HID + colbase);
        __syncthreads();

        #pragma unroll
        for (int s = 0; s < TS; s++) {
            float4 af = *(const float4*)&ks[s][ty * 4];
            float4 bf = *(const float4*)&vs[s][tx * 4];
            float a[4] = {af.x, af.y, af.z, af.w};
            float b[4] = {bf.x, bf.y, bf.z, bf.w};
            #pragma unroll
            for (int i = 0; i < 4; i++)
                #pragma unroll
                for (int j = 0; j < 4; j++)
                    acc[i][j] = fmaf(a[i], b[j], acc[i][j]);
            if (tx == 0) {
                #pragma unroll
                for (int i = 0; i < 4; i++) zacc[i] += a[i];
            }
        }
        __syncthreads();
    }

    float* mp = g_Mpart + (size_t)(chunk * NH + h) * 4096;
    #pragma unroll
    for (int i = 0; i < 4; i++)
        #pragma unroll
        for (int j = 0; j < 4; j++)
            mp[(ty * 4 + i) * 64 + tx * 4 + j] = acc[i][j];
    if (tx == 0) {
        #pragma unroll
        for (int i = 0; i < 4; i++)
            g_zpart[(size_t)chunk * Z_ELEMS + h * 64 + ty * 4 + i] = zacc[i];
    }
}

// ---------------------------------------------------------------------------
// Kernel 6: deterministic reduction of partials + add initial state.
// ---------------------------------------------------------------------------
__global__ void reduce_state_kernel(const float* __restrict__ M,
                                    const float* __restrict__ z,
                                    float* __restrict__ outM,
                                    float* __restrict__ outz) {
    int i = blockIdx.x * 256 + threadIdx.x;
    if (i < M_ELEMS) {
        int h = i >> 12;          // 4096 elems per head
        int r = i & 4095;
        float s = M[i];
        for (int c = 0; c < NCHUNK; c++)
            s += g_Mpart[(size_t)(c * NH + h) * 4096 + r];
        outM[i] = s;
    }
    if (i < Z_ELEMS) {
        float s = z[i];
        for (int c = 0; c < NCHUNK; c++)
            s += g_zpart[(size_t)c * Z_ELEMS + i];
        outz[i] = s;
    }
}

// ---------------------------------------------------------------------------
// Launch
// ---------------------------------------------------------------------------
extern "C" void kernel_launch(void* const* d_in, const int* in_sizes, int n_in,
                              void* d_out, int out_size) {
    const float* X  = (const float*)d_in[0];
    const float* M  = (const float*)d_in[1];
    const float* z  = (const float*)d_in[2];
    const float* Wq = (const float*)d_in[3];
    const float* bq = (const float*)d_in[4];
    const float* Wk = (const float*)d_in[5];
    const float* bk = (const float*)d_in[6];
    const float* Wv = (const float*)d_in[7];
    const float* bv = (const float*)d_in[8];
    const float* Wo = (const float*)d_in[9];

    float* out  = (float*)d_out;
    float* outM = out + OUT_ELEMS;
    float* outz = out + OUT_ELEMS + M_ELEMS;

    // 1. W2 = blockdiag(M) @ Wo
    build_w2_kernel<<<dim3(16, 16), 256>>>(M, Wo);
    // 2. QKV projections (raw q,k,v with bias; reference rounding order)
    gemm_qkv_kernel<<<dim3(MROWS / BM, 24), 256>>>(X, Wq, bq, Wk, bk, Wv, bv);
    // 3. den (strict sequential order) + scale q in place
    den_scale_kernel<<<dim3(MROWS / 64, NH), 256>>>(z);
    // 4. out = (q/den) @ W2
    gemm_out_kernel<<<dim3(MROWS / BM, HID / BN), 256>>>(out);
    // 5. state-update partials (deterministic)
    update_state_kernel<<<dim3(NCHUNK, NH), 256>>>();
    // 6. reduce partials + initial state
    reduce_state_kernel<<<256, 256>>>(M, z, outM, outz);
}

// round 8
// speedup vs baseline: 1.1740x; 1.1740x over previous
#include <cuda_runtime.h>
#include <math.h>

// Problem constants
#define HID   1024
#define NH    16
#define HD    64
#define MROWS 16384           // B*S = 2*8192
#define OUT_ELEMS (MROWS * HID)        // 16777216
#define M_ELEMS   (NH * HD * HD)       // 65536
#define Z_ELEMS   (NH * HD)            // 1024
#define NCHUNK 32

typedef unsigned long long u64;

// Scratch (no cudaMalloc allowed -> device globals)
__device__ float g_q[MROWS * HID];    // q (then scaled to q/den in place)
__device__ float g_k[MROWS * HID];
__device__ float g_v[MROWS * HID];
__device__ float g_W2[HID * HID];     // blockdiag(M) @ Wo
__device__ float g_Mpart[NCHUNK * NH * HD * HD];   // split-S partials
__device__ float g_zpart[NCHUNK * Z_ELEMS];

// ---------------------------------------------------------------------------
// f32x2 packed-FMA helpers (SASS FFMA2; only reachable via PTX).
// Each lane rounds exactly like scalar FFMA.rn, so per-accumulator
// k-ascending rounding order is preserved bit-exactly.
// ---------------------------------------------------------------------------
__device__ __forceinline__ u64 pack_dup(float a) {
    u64 r;
    asm("mov.b64 %0, {%1, %1};" : "=l"(r) : "f"(a));
    return r;
}
__device__ __forceinline__ void ffma2(u64& d, u64 a, u64 b) {
    asm("fma.rn.f32x2 %0, %1, %2, %0;" : "+l"(d) : "l"(a), "l"(b));
}
__device__ __forceinline__ void unpack2(u64 v, float& lo, float& hi) {
    asm("mov.b64 {%0, %1}, %2;" : "=f"(lo), "=f"(hi) : "l"(v));
}

// ---------------------------------------------------------------------------
// Kernel 1: W2[h*64+d, n] = sum_e M[h,d,e] * Wo[h*64+e, n]
// ---------------------------------------------------------------------------
__global__ void build_w2_kernel(const float* __restrict__ Mm,
                                const float* __restrict__ Wo) {
    __shared__ float Ms[64][64];
    __shared__ float Ws[64][64];
    const int h  = blockIdx.y;
    const int nb = blockIdx.x * 64;
    const int tid = threadIdx.x;

    for (int i = tid; i < 4096; i += 256)
        Ms[i >> 6][i & 63] = Mm[h * 4096 + i];
    for (int i = tid; i < 4096; i += 256)
        Ws[i >> 6][i & 63] = Wo[(size_t)(h * 64 + (i >> 6)) * HID + nb + (i & 63)];
    __syncthreads();

    const int nn = tid & 63;
    const int dg = tid >> 6;   // 0..3
    for (int d = dg; d < 64; d += 4) {
        float s = 0.f;
        #pragma unroll 16
        for (int e = 0; e < 64; e++) s += Ms[d][e] * Ws[e][nn];
        g_W2[(size_t)(h * 64 + d) * HID + nb + nn] = s;
    }
}

// ---------------------------------------------------------------------------
// Big-GEMM tile config: 128x128 tile, BK=16, 256 threads, 8x8 per thread.
// Double-buffered smem, register prefetch, f32x2 inner product.
// ---------------------------------------------------------------------------
#define BM 128
#define BN 128
#define BKD 16
#define TM 8
#define TN 8

// Shared mainloop body (macro-free: duplicated in the two kernels for clarity)

// ---------------------------------------------------------------------------
// Kernel 2: fused QKV GEMM. C = X @ W + b for W in {Wq,Wk,Wv}.
// Accumulation strictly k-ascending, single accumulator, FFMA(.f32x2) —
// matches the reference's fp32 gemm rounding order so q bit-matches.
// ---------------------------------------------------------------------------
__global__ __launch_bounds__(256, 2)
void gemm_qkv_kernel(const float* __restrict__ X,
                     const float* __restrict__ Wq, const float* __restrict__ Bq,
                     const float* __restrict__ Wk, const float* __restrict__ Bk,
                     const float* __restrict__ Wv, const float* __restrict__ Bv) {
    __shared__ float As[2][BKD][BM];
    __shared__ float Bs[2][BKD][BN];

    const int bm    = blockIdx.x * BM;
    const int nt    = blockIdx.y;
    const int which = nt >> 3;            // 0=q 1=k 2=v
    const int bn    = (nt & 7) * BN;

    const float* W    = (which == 0) ? Wq : (which == 1) ? Wk : Wv;
    const float* Bias = (which == 0) ? Bq : (which == 1) ? Bk : Bv;
    float*       Out  = (which == 0) ? g_q : (which == 1) ? g_k : g_v;

    const int tid = threadIdx.x;
    const int tx  = tid & 15;             // n-group
    const int ty  = tid >> 4;             // m-group

    // A loads: 128 rows x 16 k = 2048 floats -> 2 float4/thread
    const int arow  = tid >> 1;
    const int akcol = (tid & 1) * 4;      // plus +8 for second
    // B loads: 16 k x 128 n -> 2 float4/thread
    const int bkrow = tid >> 5;           // plus +8 for second
    const int bncol = (tid & 31) * 4;

    const float* Aptr = X + (size_t)(bm + arow) * HID + akcol;
    const float* Wptr = W + (size_t)bkrow * HID + bn + bncol;

    u64 acc2[TM][TN / 2];
    #pragma unroll
    for (int i = 0; i < TM; i++)
        #pragma unroll
        for (int j = 0; j < TN / 2; j++) acc2[i][j] = 0ull;

    // prologue: stage 0
    {
        float4 a0 = *(const float4*)(Aptr);
        float4 a1 = *(const float4*)(Aptr + 8);
        float4 b0 = *(const float4*)(Wptr);
        float4 b1 = *(const float4*)(Wptr + (size_t)8 * HID);
        As[0][akcol + 0][arow] = a0.x; As[0][akcol + 1][arow] = a0.y;
        As[0][akcol + 2][arow] = a0.z; As[0][akcol + 3][arow] = a0.w;
        As[0][akcol + 8][arow] = a1.x; As[0][akcol + 9][arow] = a1.y;
        As[0][akcol +10][arow] = a1.z; As[0][akcol +11][arow] = a1.w;
        *(float4*)&Bs[0][bkrow    ][bncol] = b0;
        *(float4*)&Bs[0][bkrow + 8][bncol] = b1;
    }
    __syncthreads();

    int cur = 0;
    for (int k0 = BKD; k0 < HID; k0 += BKD) {
        // prefetch next block into registers
        float4 a0 = *(const float4*)(Aptr + k0);
        float4 a1 = *(const float4*)(Aptr + k0 + 8);
        float4 b0 = *(const float4*)(Wptr + (size_t)k0 * HID);
        float4 b1 = *(const float4*)(Wptr + (size_t)(k0 + 8) * HID);

        #pragma unroll
        for (int kk = 0; kk < BKD; kk++) {
            ulonglong2 bp01 = *(const ulonglong2*)&Bs[cur][kk][tx * TN];
            ulonglong2 bp23 = *(const ulonglong2*)&Bs[cur][kk][tx * TN + 4];
            float4 av0 = *(const float4*)&As[cur][kk][ty * TM];
            float4 av1 = *(const float4*)&As[cur][kk][ty * TM + 4];
            float a[TM] = {av0.x, av0.y, av0.z, av0.w, av1.x, av1.y, av1.z, av1.w};
            #pragma unroll
            for (int i = 0; i < TM; i++) {
                u64 ap = pack_dup(a[i]);
                ffma2(acc2[i][0], ap, bp01.x);
                ffma2(acc2[i][1], ap, bp01.y);
                ffma2(acc2[i][2], ap, bp23.x);
                ffma2(acc2[i][3], ap, bp23.y);
            }
        }

        const int nxt = cur ^ 1;
        As[nxt][akcol + 0][arow] = a0.x; As[nxt][akcol + 1][arow] = a0.y;
        As[nxt][akcol + 2][arow] = a0.z; As[nxt][akcol + 3][arow] = a0.w;
        As[nxt][akcol + 8][arow] = a1.x; As[nxt][akcol + 9][arow] = a1.y;
        As[nxt][akcol +10][arow] = a1.z; As[nxt][akcol +11][arow] = a1.w;
        *(float4*)&Bs[nxt][bkrow    ][bncol] = b0;
        *(float4*)&Bs[nxt][bkrow + 8][bncol] = b1;
        __syncthreads();
        cur = nxt;
    }

    // final block
    #pragma unroll
    for (int kk = 0; kk < BKD; kk++) {
        ulonglong2 bp01 = *(const ulonglong2*)&Bs[cur][kk][tx * TN];
        ulonglong2 bp23 = *(const ulonglong2*)&Bs[cur][kk][tx * TN + 4];
        float4 av0 = *(const float4*)&As[cur][kk][ty * TM];
        float4 av1 = *(const float4*)&As[cur][kk][ty * TM + 4];
        float a[TM] = {av0.x, av0.y, av0.z, av0.w, av1.x, av1.y, av1.z, av1.w};
        #pragma unroll
        for (int i = 0; i < TM; i++) {
            u64 ap = pack_dup(a[i]);
            ffma2(acc2[i][0], ap, bp01.x);
            ffma2(acc2[i][1], ap, bp01.y);
            ffma2(acc2[i][2], ap, bp23.x);
            ffma2(acc2[i][3], ap, bp23.y);
        }
    }

    // unpack + bias
    float acc[TM][TN];
    #pragma unroll
    for (int i = 0; i < TM; i++)
        #pragma unroll
        for (int j = 0; j < TN / 2; j++)
            unpack2(acc2[i][j], acc[i][2 * j], acc[i][2 * j + 1]);

    float bias[TN];
    #pragma unroll
    for (int j = 0; j < TN; j++) bias[j] = Bias[bn + tx * TN + j];
    #pragma unroll
    for (int i = 0; i < TM; i++)
        #pragma unroll
        for (int j = 0; j < TN; j++) acc[i][j] += bias[j];

    #pragma unroll
    for (int i = 0; i < TM; i++) {
        float* o = Out + (size_t)(bm + ty * TM + i) * HID + bn + tx * TN;
        *(float4*)(o)     = make_float4(acc[i][0], acc[i][1], acc[i][2], acc[i][3]);
        *(float4*)(o + 4) = make_float4(acc[i][4], acc[i][5], acc[i][6], acc[i][7]);
    }
}

// ---------------------------------------------------------------------------
// Kernel 3: den + scale. For each (row, head): den = |sum_d q[d]*z[d]| + eps
// with a STRICT sequential d=0..63 fmaf chain (matches reference reduction
// order), then q <- q * (1/den) in place.
// ---------------------------------------------------------------------------
__global__ __launch_bounds__(256, 4)
void den_scale_kernel(const float* __restrict__ Z) {
    __shared__ float tile[64][65];
    __shared__ float zsh[64];
    __shared__ float inv[64];

    const int h   = blockIdx.y;
    const int r0  = blockIdx.x * 64;
    const int tid = threadIdx.x;
    const size_t base = (size_t)r0 * HID + h * 64;

    if (tid < 64) zsh[tid] = Z[h * 64 + tid];

    #pragma unroll
    for (int t = 0; t < 4; t++) {
        int idx = tid + t * 256;
        int r   = idx >> 4;
        int c4  = (idx & 15) * 4;
        float4 v = *(const float4*)(g_q + base + (size_t)r * HID + c4);
        tile[r][c4 + 0] = v.x;
        tile[r][c4 + 1] = v.y;
        tile[r][c4 + 2] = v.z;
        tile[r][c4 + 3] = v.w;
    }
    __syncthreads();

    if (tid < 64) {
        float s = 0.f;
        for (int d = 0; d < 64; d++)
            s = fmaf(tile[tid][d], zsh[d], s);
        inv[tid] = 1.f / (fabsf(s) + 1e-6f);
    }
    __syncthreads();

    #pragma unroll
    for (int t = 0; t < 4; t++) {
        int idx = tid + t * 256;
        int r   = idx >> 4;
        int c4  = (idx & 15) * 4;
        float iv = inv[r];
        float4 v;
        v.x = tile[r][c4 + 0] * iv;
        v.y = tile[r][c4 + 1] * iv;
        v.z = tile[r][c4 + 2] * iv;
        v.w = tile[r][c4 + 3] * iv;
        *(float4*)(g_q + base + (size_t)r * HID + c4) = v;
    }
}

// ---------------------------------------------------------------------------
// Kernel 4: out = (q/den) @ W2   [16384,1024] x [1024,1024]
// ---------------------------------------------------------------------------
__global__ __launch_bounds__(256, 2)
void gemm_out_kernel(float* __restrict__ Out) {
    __shared__ float As[2][BKD][BM];
    __shared__ float Bs[2][BKD][BN];

    const int bm = blockIdx.x * BM;
    const int bn = blockIdx.y * BN;

    const int tid = threadIdx.x;
    const int tx  = tid & 15;
    const int ty  = tid >> 4;

    const int arow  = tid >> 1;
    const int akcol = (tid & 1) * 4;
    const int bkrow = tid >> 5;
    const int bncol = (tid & 31) * 4;

    const float* Aptr = g_q  + (size_t)(bm + arow) * HID + akcol;
    const float* Wptr = g_W2 + (size_t)bkrow * HID + bn + bncol;

    u64 acc2[TM][TN / 2];
    #pragma unroll
    for (int i = 0; i < TM; i++)
        #pragma unroll
        for (int j = 0; j < TN / 2; j++) acc2[i][j] = 0ull;

    {
        float4 a0 = *(const float4*)(Aptr);
        float4 a1 = *(const float4*)(Aptr + 8);
        float4 b0 = *(const float4*)(Wptr);
        float4 b1 = *(const float4*)(Wptr + (size_t)8 * HID);
        As[0][akcol + 0][arow] = a0.x; As[0][akcol + 1][arow] = a0.y;
        As[0][akcol + 2][arow] = a0.z; As[0][akcol + 3][arow] = a0.w;
        As[0][akcol + 8][arow] = a1.x; As[0][akcol + 9][arow] = a1.y;
        As[0][akcol +10][arow] = a1.z; As[0][akcol +11][arow] = a1.w;
        *(float4*)&Bs[0][bkrow    ][bncol] = b0;
        *(float4*)&Bs[0][bkrow + 8][bncol] = b1;
    }
    __syncthreads();

    int cur = 0;
    for (int k0 = BKD; k0 < HID; k0 += BKD) {
        float4 a0 = *(const float4*)(Aptr + k0);
        float4 a1 = *(const float4*)(Aptr + k0 + 8);
        float4 b0 = *(const float4*)(Wptr + (size_t)k0 * HID);
        float4 b1 = *(const float4*)(Wptr + (size_t)(k0 + 8) * HID);

        #pragma unroll
        for (int kk = 0; kk < BKD; kk++) {
            ulonglong2 bp01 = *(const ulonglong2*)&Bs[cur][kk][tx * TN];
            ulonglong2 bp23 = *(const ulonglong2*)&Bs[cur][kk][tx * TN + 4];
            float4 av0 = *(const float4*)&As[cur][kk][ty * TM];
            float4 av1 = *(const float4*)&As[cur][kk][ty * TM + 4];
            float a[TM] = {av0.x, av0.y, av0.z, av0.w, av1.x, av1.y, av1.z, av1.w};
            #pragma unroll
            for (int i = 0; i < TM; i++) {
                u64 ap = pack_dup(a[i]);
                ffma2(acc2[i][0], ap, bp01.x);
                ffma2(acc2[i][1], ap, bp01.y);
                ffma2(acc2[i][2], ap, bp23.x);
                ffma2(acc2[i][3], ap, bp23.y);
            }
        }

        const int nxt = cur ^ 1;
        As[nxt][akcol + 0][arow] = a0.x; As[nxt][akcol + 1][arow] = a0.y;
        As[nxt][akcol + 2][arow] = a0.z; As[nxt][akcol + 3][arow] = a0.w;
        As[nxt][akcol + 8][arow] = a1.x; As[nxt][akcol + 9][arow] = a1.y;
        As[nxt][akcol +10][arow] = a1.z; As[nxt][akcol +11][arow] = a1.w;
        *(float4*)&Bs[nxt][bkrow    ][bncol] = b0;
        *(float4*)&Bs[nxt][bkrow + 8][bncol] = b1;
        __syncthreads();
        cur = nxt;
    }

    #pragma unroll
    for (int kk = 0; kk < BKD; kk++) {
        ulonglong2 bp01 = *(const ulonglong2*)&Bs[cur][kk][tx * TN];
        ulonglong2 bp23 = *(const ulonglong2*)&Bs[cur][kk][tx * TN + 4];
        float4 av0 = *(const float4*)&As[cur][kk][ty * TM];
        float4 av1 = *(const float4*)&As[cur][kk][ty * TM + 4];
        float a[TM] = {av0.x, av0.y, av0.z, av0.w, av1.x, av1.y, av1.z, av1.w};
        #pragma unroll
        for (int i = 0; i < TM; i++) {
            u64 ap = pack_dup(a[i]);
            ffma2(acc2[i][0], ap, bp01.x);
            ffma2(acc2[i][1], ap, bp01.y);
            ffma2(acc2[i][2], ap, bp23.x);
            ffma2(acc2[i][3], ap, bp23.y);
        }
    }

    #pragma unroll
    for (int i = 0; i < TM; i++) {
        float r0, r1, r2, r3, r4, r5, r6, r7;
        unpack2(acc2[i][0], r0, r1);
        unpack2(acc2[i][1], r2, r3);
        unpack2(acc2[i][2], r4, r5);
        unpack2(acc2[i][3], r6, r7);
        float* o = Out + (size_t)(bm + ty * TM + i) * HID + bn + tx * TN;
        *(float4*)(o)     = make_float4(r0, r1, r2, r3);
        *(float4*)(o + 4) = make_float4(r4, r5, r6, r7);
    }
}

// ---------------------------------------------------------------------------
// Kernel 5: split-S partials of sum_s k (x) v and sum_s k per head.
// Deterministic: partials go to g_Mpart/g_zpart (no atomics).
// ---------------------------------------------------------------------------
#define TS 16

__global__ __launch_bounds__(256, 4)
void update_state_kernel() {
    __shared__ float ks[TS][64];
    __shared__ float vs[TS][64];

    const int h      = blockIdx.y;
    const int chunk  = blockIdx.x;
    const int rows   = MROWS / NCHUNK;            // 512
    const int s_base = chunk * rows;

    const int tid = threadIdx.x;
    const int tx  = tid & 15;                     // e-group (4 cols)
    const int ty  = tid >> 4;                     // d-group (4 rows)

    const int s_l = tid >> 4;
    const int c4  = (tid & 15) * 4;

    float acc[4][4];
    #pragma unroll
    for (int i = 0; i < 4; i++)
        #pragma unroll
        for (int j = 0; j < 4; j++) acc[i][j] = 0.f;
    float zacc[4] = {0.f, 0.f, 0.f, 0.f};

    const size_t colbase = (size_t)h * 64 + c4;

    for (int s0 = s_base; s0 < s_base + rows; s0 += TS) {
        *(float4*)&ks[s_l][c4] = *(const float4*)(g_k + (size_t)(s0 + s_l) * HID + colbase);
        *(float4*)&vs[s_l][c4] = *(const float4*)(g_v + (size_t)(s0 + s_l) * HID + colbase);
        __syncthreads();

        #pragma unroll
        for (int s = 0; s < TS; s++) {
            float4 af = *(const float4*)&ks[s][ty * 4];
            float4 bf = *(const float4*)&vs[s][tx * 4];
            float a[4] = {af.x, af.y, af.z, af.w};
            float b[4] = {bf.x, bf.y, bf.z, bf.w};
            #pragma unroll
            for (int i = 0; i < 4; i++)
                #pragma unroll
                for (int j = 0; j < 4; j++)
                    acc[i][j] = fmaf(a[i], b[j], acc[i][j]);
            if (tx == 0) {
                #pragma unroll
                for (int i = 0; i < 4; i++) zacc[i] += a[i];
            }
        }
        __syncthreads();
    }

    float* mp = g_Mpart + (size_t)(chunk * NH + h) * 4096;
    #pragma unroll
    for (int i = 0; i < 4; i++)
        #pragma unroll
        for (int j = 0; j < 4; j++)
            mp[(ty * 4 + i) * 64 + tx * 4 + j] = acc[i][j];
    if (tx == 0) {
        #pragma unroll
        for (int i = 0; i < 4; i++)
            g_zpart[(size_t)chunk * Z_ELEMS + h * 64 + ty * 4 + i] = zacc[i];
    }
}

// ---------------------------------------------------------------------------
// Kernel 6: deterministic reduction of partials + add initial state.
// ---------------------------------------------------------------------------
__global__ void reduce_state_kernel(const float* __restrict__ M,
                                    const float* __restrict__ z,
                                    float* __restrict__ outM,
                                    float* __restrict__ outz) {
    int i = blockIdx.x * 256 + threadIdx.x;
    if (i < M_ELEMS) {
        int h = i >> 12;
        int r = i & 4095;
        float s = M[i];
        for (int c = 0; c < NCHUNK; c++)
            s += g_Mpart[(size_t)(c * NH + h) * 4096 + r];
        outM[i] = s;
    }
    if (i < Z_ELEMS) {
        float s = z[i];
        for (int c = 0; c < NCHUNK; c++)
            s += g_zpart[(size_t)c * Z_ELEMS + i];
        outz[i] = s;
    }
}

// ---------------------------------------------------------------------------
// Launch
// ---------------------------------------------------------------------------
extern "C" void kernel_launch(void* const* d_in, const int* in_sizes, int n_in,
                              void* d_out, int out_size) {
    const float* X  = (const float*)d_in[0];
    const float* M  = (const float*)d_in[1];
    const float* z  = (const float*)d_in[2];
    const float* Wq = (const float*)d_in[3];
    const float* bq = (const float*)d_in[4];
    const float* Wk = (const float*)d_in[5];
    const float* bk = (const float*)d_in[6];
    const float* Wv = (const float*)d_in[7];
    const float* bv = (const float*)d_in[8];
    const float* Wo = (const float*)d_in[9];

    float* out  = (float*)d_out;
    float* outM = out + OUT_ELEMS;
    float* outz = out + OUT_ELEMS + M_ELEMS;

    // 1. W2 = blockdiag(M) @ Wo
    build_w2_kernel<<<dim3(16, 16), 256>>>(M, Wo);
    // 2. QKV projections (raw q,k,v with bias; reference rounding order)
    gemm_qkv_kernel<<<dim3(MROWS / BM, 24), 256>>>(X, Wq, bq, Wk, bk, Wv, bv);
    // 3. den (strict sequential order) + scale q in place
    den_scale_kernel<<<dim3(MROWS / 64, NH), 256>>>(z);
    // 4. out = (q/den) @ W2
    gemm_out_kernel<<<dim3(MROWS / BM, HID / BN), 256>>>(out);
    // 5. state-update partials (deterministic)
    update_state_kernel<<<dim3(NCHUNK, NH), 256>>>();
    // 6. reduce partials + initial state
    reduce_state_kernel<<<256, 256>>>(M, z, outM, outz);
}

// round 11
// speedup vs baseline: 1.3040x; 1.1107x over previous
#include <cuda_runtime.h>
#include <math.h>

// Problem constants
#define HID   1024
#define NH    16
#define HD    64
#define MROWS 16384           // B*S = 2*8192
#define OUT_ELEMS (MROWS * HID)        // 16777216
#define M_ELEMS   (NH * HD * HD)       // 65536
#define Z_ELEMS   (NH * HD)            // 1024
#define NCHUNK 32

typedef unsigned long long u64;

// Scratch (no cudaMalloc allowed -> device globals)
__device__ float g_q[MROWS * HID];    // q (then scaled to q/den in place)
__device__ float g_k[MROWS * HID];
__device__ float g_v[MROWS * HID];
__device__ float g_W2[HID * HID];     // blockdiag(M) @ Wo
__device__ float g_Mpart[NCHUNK * NH * HD * HD];   // split-S partials
__device__ float g_zpart[NCHUNK * Z_ELEMS];

// ---------------------------------------------------------------------------
// f32x2 packed-FMA helpers (SASS FFMA2; only reachable via PTX).
// Each lane rounds exactly like scalar FFMA.rn, so per-accumulator
// k-ascending rounding order is preserved bit-exactly.
// ---------------------------------------------------------------------------
__device__ __forceinline__ u64 pack_dup(float a) {
    u64 r;
    asm("mov.b64 %0, {%1, %1};" : "=l"(r) : "f"(a));
    return r;
}
__device__ __forceinline__ void ffma2(u64& d, u64 a, u64 b) {
    asm("fma.rn.f32x2 %0, %1, %2, %0;" : "+l"(d) : "l"(a), "l"(b));
}
__device__ __forceinline__ void unpack2(u64 v, float& lo, float& hi) {
    asm("mov.b64 {%0, %1}, %2;" : "=f"(lo), "=f"(hi) : "l"(v));
}

// ---------------------------------------------------------------------------
// Kernel 1: W2[h*64+d, n] = sum_e M[h,d,e] * Wo[h*64+e, n]
// ---------------------------------------------------------------------------
__global__ void build_w2_kernel(const float* __restrict__ Mm,
                                const float* __restrict__ Wo) {
    __shared__ float Ms[64][64];
    __shared__ float Ws[64][64];
    const int h  = blockIdx.y;
    const int nb = blockIdx.x * 64;
    const int tid = threadIdx.x;

    for (int i = tid; i < 4096; i += 256)
        Ms[i >> 6][i & 63] = Mm[h * 4096 + i];
    for (int i = tid; i < 4096; i += 256)
        Ws[i >> 6][i & 63] = Wo[(size_t)(h * 64 + (i >> 6)) * HID + nb + (i & 63)];
    __syncthreads();

    const int nn = tid & 63;
    const int dg = tid >> 6;   // 0..3
    for (int d = dg; d < 64; d += 4) {
        float s = 0.f;
        #pragma unroll 16
        for (int e = 0; e < 64; e++) s += Ms[d][e] * Ws[e][nn];
        g_W2[(size_t)(h * 64 + d) * HID + nb + nn] = s;
    }
}

// ---------------------------------------------------------------------------
// Big-GEMM tile: BM=128, BN=256, BK=16, 256 threads, 8x16 per thread.
// B tile stored as [BK][4][16] float4 blocks where block [j][t] holds
// columns j*64 + t*4 .. +3 (relative to bn).
// Thread tx therefore owns columns {4tx, 64+4tx, 128+4tx, 192+4tx} (+0..3).
// Reads (granule tx of each block): 16 distinct 16B granules/phase with
// 2-lane broadcast -> conflict-free. Staging writes are 32 consecutive
// granules per warp -> conflict-free. A tile [BK][BM]; A reads broadcast.
// ---------------------------------------------------------------------------
#define BM 128
#define BN 256
#define BKD 16
#define TM 8
#define TN 16

struct BTile { float4 b[BKD][4][16]; };

__device__ __forceinline__
void gemm_core_128x256(const float* __restrict__ Aglob,   // row-major [.,HID], tile origin applied
                       const float* __restrict__ Wglob,   // [HID, HID], col origin applied
                       float* __restrict__ Outp,          // tile origin applied
                       const float* __restrict__ Bias)    // may be null; origin applied
{
    __shared__ float As[2][BKD][BM];
    __shared__ BTile Bs[2];

    const int tid = threadIdx.x;
    const int tx  = tid & 15;             // n-group
    const int ty  = tid >> 4;             // m-group (8 rows each)

    // A staging: 128 rows x 16 k = 2048 floats -> 2 float4/thread
    const int arow  = tid >> 1;
    const int akcol = (tid & 1) * 4;      // plus +8 for second
    // B staging: 16 k x 256 n = 4096 floats -> 4 float4/thread
    const int bkrow = tid >> 5;           // 0..7, plus +8
    const int c4    = tid & 31;           // float4 column index; plus +32

    const float* Aptr = Aglob + (size_t)arow * HID + akcol;
    const float* Wp0  = Wglob + (size_t)bkrow * HID + c4 * 4;
    const float* Wp1  = Wglob + (size_t)bkrow * HID + c4 * 4 + 128;
    const float* Wp2  = Wglob + (size_t)(bkrow + 8) * HID + c4 * 4;
    const float* Wp3  = Wglob + (size_t)(bkrow + 8) * HID + c4 * 4 + 128;

    u64 acc2[TM][TN / 2];
    #pragma unroll
    for (int i = 0; i < TM; i++)
        #pragma unroll
        for (int j = 0; j < TN / 2; j++) acc2[i][j] = 0ull;

    // prologue: stage 0
    {
        float4 a0 = *(const float4*)(Aptr);
        float4 a1 = *(const float4*)(Aptr + 8);
        float4 b0 = *(const float4*)(Wp0);
        float4 b1 = *(const float4*)(Wp1);
        float4 b2 = *(const float4*)(Wp2);
        float4 b3 = *(const float4*)(Wp3);
        As[0][akcol + 0][arow] = a0.x; As[0][akcol + 1][arow] = a0.y;
        As[0][akcol + 2][arow] = a0.z; As[0][akcol + 3][arow] = a0.w;
        As[0][akcol + 8][arow] = a1.x; As[0][akcol + 9][arow] = a1.y;
        As[0][akcol +10][arow] = a1.z; As[0][akcol +11][arow] = a1.w;
        Bs[0].b[bkrow    ][c4 >> 4      ][c4 & 15] = b0;
        Bs[0].b[bkrow    ][(c4 >> 4) + 2][c4 & 15] = b1;
        Bs[0].b[bkrow + 8][c4 >> 4      ][c4 & 15] = b2;
        Bs[0].b[bkrow + 8][(c4 >> 4) + 2][c4 & 15] = b3;
    }
    __syncthreads();

    int cur = 0;
    for (int k0 = BKD; k0 <= HID; k0 += BKD) {
        float4 a0, a1, b0, b1, b2, b3;
        const bool more = (k0 < HID);
        if (more) {
            a0 = *(const float4*)(Aptr + k0);
            a1 = *(const float4*)(Aptr + k0 + 8);
            b0 = *(const float4*)(Wp0 + (size_t)k0 * HID);
            b1 = *(const float4*)(Wp1 + (size_t)k0 * HID);
            b2 = *(const float4*)(Wp2 + (size_t)k0 * HID);
            b3 = *(const float4*)(Wp3 + (size_t)k0 * HID);
        }

        #pragma unroll
        for (int kk = 0; kk < BKD; kk++) {
            ulonglong2 q0 = *(const ulonglong2*)&Bs[cur].b[kk][0][tx];
            ulonglong2 q1 = *(const ulonglong2*)&Bs[cur].b[kk][1][tx];
            ulonglong2 q2 = *(const ulonglong2*)&Bs[cur].b[kk][2][tx];
            ulonglong2 q3 = *(const ulonglong2*)&Bs[cur].b[kk][3][tx];
            float4 av0 = *(const float4*)&As[cur][kk][ty * TM];
            float4 av1 = *(const float4*)&As[cur][kk][ty * TM + 4];
            float a[TM] = {av0.x, av0.y, av0.z, av0.w, av1.x, av1.y, av1.z, av1.w};
            #pragma unroll
            for (int i = 0; i < TM; i++) {
                u64 ap = pack_dup(a[i]);
                ffma2(acc2[i][0], ap, q0.x);
                ffma2(acc2[i][1], ap, q0.y);
                ffma2(acc2[i][2], ap, q1.x);
                ffma2(acc2[i][3], ap, q1.y);
                ffma2(acc2[i][4], ap, q2.x);
                ffma2(acc2[i][5], ap, q2.y);
                ffma2(acc2[i][6], ap, q3.x);
                ffma2(acc2[i][7], ap, q3.y);
            }
        }

        if (more) {
            const int nxt = cur ^ 1;
            As[nxt][akcol + 0][arow] = a0.x; As[nxt][akcol + 1][arow] = a0.y;
            As[nxt][akcol + 2][arow] = a0.z; As[nxt][akcol + 3][arow] = a0.w;
            As[nxt][akcol + 8][arow] = a1.x; As[nxt][akcol + 9][arow] = a1.y;
            As[nxt][akcol +10][arow] = a1.z; As[nxt][akcol +11][arow] = a1.w;
            Bs[nxt].b[bkrow    ][c4 >> 4      ][c4 & 15] = b0;
            Bs[nxt].b[bkrow    ][(c4 >> 4) + 2][c4 & 15] = b1;
            Bs[nxt].b[bkrow + 8][c4 >> 4      ][c4 & 15] = b2;
            Bs[nxt].b[bkrow + 8][(c4 >> 4) + 2][c4 & 15] = b3;
            __syncthreads();
            cur = nxt;
        }
    }

    // Epilogue: acc2[i][2g],acc2[i][2g+1] hold columns g*64 + 4*tx .. +3.
    // Bias preloaded per column group; stores coalesced (16 lanes x 16B runs).
    float bias[4][4];
    if (Bias) {
        #pragma unroll
        for (int g = 0; g < 4; g++) {
            float4 bv = *(const float4*)(Bias + g * 64 + 4 * tx);
            bias[g][0] = bv.x; bias[g][1] = bv.y; bias[g][2] = bv.z; bias[g][3] = bv.w;
        }
    }

    #pragma unroll
    for (int i = 0; i < TM; i++) {
        float* orow = Outp + (size_t)(ty * TM + i) * HID;
        #pragma unroll
        for (int g = 0; g < 4; g++) {
            float r0, r1, r2, r3;
            unpack2(acc2[i][2 * g],     r0, r1);
            unpack2(acc2[i][2 * g + 1], r2, r3);
            if (Bias) {
                r0 += bias[g][0]; r1 += bias[g][1];
                r2 += bias[g][2]; r3 += bias[g][3];
            }
            *(float4*)(orow + g * 64 + 4 * tx) = make_float4(r0, r1, r2, r3);
        }
    }
}

// ---------------------------------------------------------------------------
// Kernel 2: fused QKV GEMM. grid (MROWS/BM, 12): which = nt>>2, bn = (nt&3)*256
// Accumulation strictly k-ascending, single accumulator per output,
// FFMA(.f32x2) — matches reference fp32 gemm rounding order (q bit-matches).
// ---------------------------------------------------------------------------
__global__ __launch_bounds__(256, 1)
void gemm_qkv_kernel(const float* __restrict__ X,
                     const float* __restrict__ Wq, const float* __restrict__ Bq,
                     const float* __restrict__ Wk, const float* __restrict__ Bk,
                     const float* __restrict__ Wv, const float* __restrict__ Bv) {
    const int bm    = blockIdx.x * BM;
    const int nt    = blockIdx.y;
    const int which = nt >> 2;            // 0=q 1=k 2=v
    const int bn    = (nt & 3) * BN;

    const float* W    = (which == 0) ? Wq : (which == 1) ? Wk : Wv;
    const float* Bias = (which == 0) ? Bq : (which == 1) ? Bk : Bv;
    float*       Out  = (which == 0) ? g_q : (which == 1) ? g_k : g_v;

    gemm_core_128x256(X + (size_t)bm * HID,
                      W + bn,
                      Out + (size_t)bm * HID + bn,
                      Bias + bn);
}

// ---------------------------------------------------------------------------
// Kernel 3: den + scale. For each (row, head): den = |sum_d q[d]*z[d]| + eps
// with a STRICT sequential d=0..63 fmaf chain (matches reference reduction
// order), then q <- q * (1/den) in place.
// ---------------------------------------------------------------------------
__global__ __launch_bounds__(256, 4)
void den_scale_kernel(const float* __restrict__ Z) {
    __shared__ float tile[64][65];
    __shared__ float zsh[64];
    __shared__ float inv[64];

    const int h   = blockIdx.y;
    const int r0  = blockIdx.x * 64;
    const int tid = threadIdx.x;
    const size_t base = (size_t)r0 * HID + h * 64;

    if (tid < 64) zsh[tid] = Z[h * 64 + tid];

    #pragma unroll
    for (int t = 0; t < 4; t++) {
        int idx = tid + t * 256;
        int r   = idx >> 4;
        int c4  = (idx & 15) * 4;
        float4 v = *(const float4*)(g_q + base + (size_t)r * HID + c4);
        tile[r][c4 + 0] = v.x;
        tile[r][c4 + 1] = v.y;
        tile[r][c4 + 2] = v.z;
        tile[r][c4 + 3] = v.w;
    }
    __syncthreads();

    if (tid < 64) {
        float s = 0.f;
        for (int d = 0; d < 64; d++)
            s = fmaf(tile[tid][d], zsh[d], s);
        inv[tid] = 1.f / (fabsf(s) + 1e-6f);
    }
    __syncthreads();

    #pragma unroll
    for (int t = 0; t < 4; t++) {
        int idx = tid + t * 256;
        int r   = idx >> 4;
        int c4  = (idx & 15) * 4;
        float iv = inv[r];
        float4 v;
        v.x = tile[r][c4 + 0] * iv;
        v.y = tile[r][c4 + 1] * iv;
        v.z = tile[r][c4 + 2] * iv;
        v.w = tile[r][c4 + 3] * iv;
        *(float4*)(g_q + base + (size_t)r * HID + c4) = v;
    }
}

// ---------------------------------------------------------------------------
// Kernel 4: out = (q/den) @ W2   [16384,1024] x [1024,1024]
// ---------------------------------------------------------------------------
__global__ __launch_bounds__(256, 1)
void gemm_out_kernel(float* __restrict__ Out) {
    const int bm = blockIdx.x * BM;
    const int bn = blockIdx.y * BN;
    gemm_core_128x256(g_q + (size_t)bm * HID,
                      g_W2 + bn,
                      Out + (size_t)bm * HID + bn,
                      (const float*)0);
}

// ---------------------------------------------------------------------------
// Kernel 5: split-S partials of sum_s k (x) v and sum_s k per head.
// Deterministic: partials go to g_Mpart/g_zpart (no atomics).
// ---------------------------------------------------------------------------
#define TS 16

__global__ __launch_bounds__(256, 4)
void update_state_kernel() {
    __shared__ float ks[TS][64];
    __shared__ float vs[TS][64];

    const int h      = blockIdx.y;
    const int chunk  = blockIdx.x;
    const int rows   = MROWS / NCHUNK;            // 512
    const int s_base = chunk * rows;

    const int tid = threadIdx.x;
    const int tx  = tid & 15;                     // e-group (4 cols)
    const int ty  = tid >> 4;                     // d-group (4 rows)

    const int s_l = tid >> 4;
    const int c4  = (tid & 15) * 4;

    float acc[4][4];
    #pragma unroll
    for (int i = 0; i < 4; i++)
        #pragma unroll
        for (int j = 0; j < 4; j++) acc[i][j] = 0.f;
    float zacc[4] = {0.f, 0.f, 0.f, 0.f};

    const size_t colbase = (size_t)h * 64 + c4;

    for (int s0 = s_base; s0 < s_base + rows; s0 += TS) {
        *(float4*)&ks[s_l][c4] = *(const float4*)(g_k + (size_t)(s0 + s_l) * HID + colbase);
        *(float4*)&vs[s_l][c4] = *(const float4*)(g_v + (size_t)(s0 + s_l) * HID + colbase);
        __syncthreads();

        #pragma unroll
        for (int s = 0; s < TS; s++) {
            float4 af = *(const float4*)&ks[s][ty * 4];
            float4 bf = *(const float4*)&vs[s][tx * 4];
            float a[4] = {af.x, af.y, af.z, af.w};
            float b[4] = {bf.x, bf.y, bf.z, bf.w};
            #pragma unroll
            for (int i = 0; i < 4; i++)
                #pragma unroll
                for (int j = 0; j < 4; j++)
                    acc[i][j] = fmaf(a[i], b[j], acc[i][j]);
            if (tx == 0) {
                #pragma unroll
                for (int i = 0; i < 4; i++) zacc[i] += a[i];
            }
        }
        __syncthreads();
    }

    float* mp = g_Mpart + (size_t)(chunk * NH + h) * 4096;
    #pragma unroll
    for (int i = 0; i < 4; i++)
        #pragma unroll
        for (int j = 0; j < 4; j++)
            mp[(ty * 4 + i) * 64 + tx * 4 + j] = acc[i][j];
    if (tx == 0) {
        #pragma unroll
        for (int i = 0; i < 4; i++)
            g_zpart[(size_t)chunk * Z_ELEMS + h * 64 + ty * 4 + i] = zacc[i];
    }
}

// ---------------------------------------------------------------------------
// Kernel 6: deterministic reduction of partials + add initial state.
// ---------------------------------------------------------------------------
__global__ void reduce_state_kernel(const float* __restrict__ M,
                                    const float* __restrict__ z,
                                    float* __restrict__ outM,
                                    float* __restrict__ outz) {
    int i = blockIdx.x * 256 + threadIdx.x;
    if (i < M_ELEMS) {
        int h = i >> 12;
        int r = i & 4095;
        float s = M[i];
        for (int c = 0; c < NCHUNK; c++)
            s += g_Mpart[(size_t)(c * NH + h) * 4096 + r];
        outM[i] = s;
    }
    if (i < Z_ELEMS) {
        float s = z[i];
        for (int c = 0; c < NCHUNK; c++)
            s += g_zpart[(size_t)c * Z_ELEMS + i];
        outz[i] = s;
    }
}

// ---------------------------------------------------------------------------
// Launch
// ---------------------------------------------------------------------------
extern "C" void kernel_launch(void* const* d_in, const int* in_sizes, int n_in,
                              void* d_out, int out_size) {
    const float* X  = (const float*)d_in[0];
    const float* M  = (const float*)d_in[1];
    const float* z  = (const float*)d_in[2];
    const float* Wq = (const float*)d_in[3];
    const float* bq = (const float*)d_in[4];
    const float* Wk = (const float*)d_in[5];
    const float* bk = (const float*)d_in[6];
    const float* Wv = (const float*)d_in[7];
    const float* bv = (const float*)d_in[8];
    const float* Wo = (const float*)d_in[9];

    float* out  = (float*)d_out;
    float* outM = out + OUT_ELEMS;
    float* outz = out + OUT_ELEMS + M_ELEMS;

    // 1. W2 = blockdiag(M) @ Wo
    build_w2_kernel<<<dim3(16, 16), 256>>>(M, Wo);
    // 2. QKV projections (raw q,k,v with bias; reference rounding order)
    gemm_qkv_kernel<<<dim3(MROWS / BM, 12), 256>>>(X, Wq, bq, Wk, bk, Wv, bv);
    // 3. den (strict sequential order) + scale q in place
    den_scale_kernel<<<dim3(MROWS / 64, NH), 256>>>(z);
    // 4. out = (q/den) @ W2
    gemm_out_kernel<<<dim3(MROWS / BM, HID / BN), 256>>>(out);
    // 5. state-update partials (deterministic)
    update_state_kernel<<<dim3(NCHUNK, NH), 256>>>();
    // 6. reduce partials + initial state
    reduce_state_kernel<<<256, 256>>>(M, z, outM, outz);
}

// round 13
// speedup vs baseline: 1.7470x; 1.3397x over previous
#include <cuda_runtime.h>
#include <cuda_bf16.h>
#include <math.h>
#include <stdint.h>

// Problem constants
#define HID   1024
#define NH    16
#define HD    64
#define MROWS 16384           // B*S = 2*8192
#define OUT_ELEMS (MROWS * HID)
#define M_ELEMS   (NH * HD * HD)
#define Z_ELEMS   (NH * HD)
#define NCHUNK 32

typedef unsigned long long u64;
typedef unsigned int u32;

// Scratch (no cudaMalloc -> device globals)
__device__ float g_q[MROWS * HID];
__device__ float g_k[MROWS * HID];
__device__ float g_v[MROWS * HID];
__device__ float g_W2[HID * HID];
__device__ float g_Mpart[NCHUNK * NH * HD * HD];
__device__ float g_zpart[NCHUNK * Z_ELEMS];
// bf16-split operands
__device__ __nv_bfloat16 g_Ahi[MROWS * HID];
__device__ __nv_bfloat16 g_Alo[MROWS * HID];
__device__ __nv_bfloat16 g_Wkhi[HID * HID], g_Wklo[HID * HID];   // transposed [n][k]
__device__ __nv_bfloat16 g_Wvhi[HID * HID], g_Wvlo[HID * HID];
__device__ __nv_bfloat16 g_W2hi[HID * HID], g_W2lo[HID * HID];

// ---------------------------------------------------------------------------
// f32x2 packed-FMA helpers (bit-exact FFMA.rn lanes) — q path only
// ---------------------------------------------------------------------------
__device__ __forceinline__ u64 pack_dup(float a) {
    u64 r; asm("mov.b64 %0, {%1, %1};" : "=l"(r) : "f"(a)); return r;
}
__device__ __forceinline__ void ffma2(u64& d, u64 a, u64 b) {
    asm("fma.rn.f32x2 %0, %1, %2, %0;" : "+l"(d) : "l"(a), "l"(b));
}
__device__ __forceinline__ void unpack2(u64 v, float& lo, float& hi) {
    asm("mov.b64 {%0, %1}, %2;" : "=f"(lo), "=f"(hi) : "l"(v));
}

// Warp-level bf16 MMA (sm_80+ feature; works on plain sm_103 PTX target)
__device__ __forceinline__ void mma16816(float* d, const u32* a, u32 b0, u32 b1) {
    asm volatile(
        "mma.sync.aligned.m16n8k16.row.col.f32.bf16.bf16.f32 "
        "{%0,%1,%2,%3}, {%4,%5,%6,%7}, {%8,%9}, {%0,%1,%2,%3};"
        : "+f"(d[0]), "+f"(d[1]), "+f"(d[2]), "+f"(d[3])
        : "r"(a[0]), "r"(a[1]), "r"(a[2]), "r"(a[3]), "r"(b0), "r"(b1));
}

// ---------------------------------------------------------------------------
// Kernel 1: W2[h*64+d, n] = sum_e M[h,d,e] * Wo[h*64+e, n]   (fp32)
// ---------------------------------------------------------------------------
__global__ void build_w2_kernel(const float* __restrict__ Mm,
                                const float* __restrict__ Wo) {
    __shared__ float Ms[64][64];
    __shared__ float Ws[64][64];
    const int h  = blockIdx.y;
    const int nb = blockIdx.x * 64;
    const int tid = threadIdx.x;

    for (int i = tid; i < 4096; i += 256)
        Ms[i >> 6][i & 63] = Mm[h * 4096 + i];
    for (int i = tid; i < 4096; i += 256)
        Ws[i >> 6][i & 63] = Wo[(size_t)(h * 64 + (i >> 6)) * HID + nb + (i & 63)];
    __syncthreads();

    const int nn = tid & 63;
    const int dg = tid >> 6;
    for (int d = dg; d < 64; d += 4) {
        float s = 0.f;
        #pragma unroll 16
        for (int e = 0; e < 64; e++) s += Ms[d][e] * Ws[e][nn];
        g_W2[(size_t)(h * 64 + d) * HID + nb + nn] = s;
    }
}

// ---------------------------------------------------------------------------
// fp32 -> (hi, lo) bf16 split. src==null -> read g_q.
// ---------------------------------------------------------------------------
__global__ __launch_bounds__(256)
void split_kernel(const float* __restrict__ src) {
    const float* s = src ? src : (const float*)g_q;
    int i = blockIdx.x * 256 + threadIdx.x;     // float4 index
    float4 v = ((const float4*)s)[i];
    __nv_bfloat16 h0 = __float2bfloat16_rn(v.x);
    __nv_bfloat16 h1 = __float2bfloat16_rn(v.y);
    __nv_bfloat16 h2 = __float2bfloat16_rn(v.z);
    __nv_bfloat16 h3 = __float2bfloat16_rn(v.w);
    __nv_bfloat16 l0 = __float2bfloat16_rn(v.x - __bfloat162float(h0));
    __nv_bfloat16 l1 = __float2bfloat16_rn(v.y - __bfloat162float(h1));
    __nv_bfloat16 l2 = __float2bfloat16_rn(v.z - __bfloat162float(h2));
    __nv_bfloat16 l3 = __float2bfloat16_rn(v.w - __bfloat162float(h3));
    u32 hA = (u32)__bfloat16_as_ushort(h0) | ((u32)__bfloat16_as_ushort(h1) << 16);
    u32 hB = (u32)__bfloat16_as_ushort(h2) | ((u32)__bfloat16_as_ushort(h3) << 16);
    u32 lA = (u32)__bfloat16_as_ushort(l0) | ((u32)__bfloat16_as_ushort(l1) << 16);
    u32 lB = (u32)__bfloat16_as_ushort(l2) | ((u32)__bfloat16_as_ushort(l3) << 16);
    ((uint2*)g_Ahi)[i] = make_uint2(hA, hB);
    ((uint2*)g_Alo)[i] = make_uint2(lA, lB);
}

// ---------------------------------------------------------------------------
// Weight W [k][n] fp32 -> transposed bf16 split [n][k]. which: 0=Wk 1=Wv 2=g_W2
// ---------------------------------------------------------------------------
__global__ __launch_bounds__(256)
void conv_w_kernel(const float* __restrict__ src, int which) {
    __shared__ float t[32][33];
    const float* W = src ? src : (const float*)g_W2;
    __nv_bfloat16* Thi = (which == 0) ? g_Wkhi : (which == 1) ? g_Wvhi : g_W2hi;
    __nv_bfloat16* Tlo = (which == 0) ? g_Wklo : (which == 1) ? g_Wvlo : g_W2lo;

    const int k0 = blockIdx.x * 32;
    const int n0 = blockIdx.y * 32;
    const int r  = threadIdx.x >> 5;
    const int c  = threadIdx.x & 31;

    #pragma unroll
    for (int i = 0; i < 4; i++) {
        int rr = r + i * 8;
        t[rr][c] = W[(size_t)(k0 + rr) * HID + n0 + c];
    }
    __syncthreads();
    #pragma unroll
    for (int i = 0; i < 4; i++) {
        int rr = r + i * 8;
        float v = t[c][rr];            // = W[k0+c][n0+rr]
        __nv_bfloat16 hi = __float2bfloat16_rn(v);
        __nv_bfloat16 lo = __float2bfloat16_rn(v - __bfloat162float(hi));
        Thi[(size_t)(n0 + rr) * HID + k0 + c] = hi;
        Tlo[(size_t)(n0 + rr) * HID + k0 + c] = lo;
    }
}

// ---------------------------------------------------------------------------
// bf16-split tensor-core GEMM via mma.sync.m16n8k16:
// D[128x128] = A[128x1024] x Bt[128x1024]^T, 3 terms (hihi+hilo+lohi), fp32 acc.
// Block: 256 thr = 8 warps (4 along M x 2 along N); warp tile 32x64.
// BK=32, single-buffer padded smem (row pad 8 bf16 -> conflict-free frags),
// register prefetch of next K-slab. mode: 0=k(bias) 1=v(bias) 2=out(no bias).
// ---------------------------------------------------------------------------
#define LDP 40   // padded smem row length (bf16 elems): 32 + 8

__global__ __launch_bounds__(256)
void mma_gemm_kernel(int mode, const float* __restrict__ BiasArg,
                     float* __restrict__ OutArg) {
    __shared__ __nv_bfloat16 sAhi[128][LDP], sAlo[128][LDP];
    __shared__ __nv_bfloat16 sBhi[128][LDP], sBlo[128][LDP];

    const __nv_bfloat16* Ahi = g_Ahi;
    const __nv_bfloat16* Alo = g_Alo;
    const __nv_bfloat16* Bhi = (mode == 0) ? g_Wkhi : (mode == 1) ? g_Wvhi : g_W2hi;
    const __nv_bfloat16* Blo = (mode == 0) ? g_Wklo : (mode == 1) ? g_Wvlo : g_W2lo;
    float* Out = (mode == 0) ? g_k : (mode == 1) ? g_v : OutArg;
    const float* Bias = (mode == 2) ? (const float*)0 : BiasArg;

    const int bm = blockIdx.x * 128;
    const int bn = blockIdx.y * 128;
    const int tid  = threadIdx.x;
    const int wid  = tid >> 5;
    const int lane = tid & 31;
    const int wm = wid & 3;        // M warp: rows wm*32
    const int wn = wid >> 2;       // N warp: cols wn*64
    const int grp = lane >> 2;     // 0..7
    const int qd  = lane & 3;

    // staging: thread covers row (tid>>1), k-halfslab (tid&1)*16
    const int row_s = tid >> 1;
    const int kh    = (tid & 1) * 16;
    const size_t agbase = (size_t)(bm + row_s) * HID + kh;
    const size_t bgbase = (size_t)(bn + row_s) * HID + kh;

    float acc[2][8][4];
    #pragma unroll
    for (int mt = 0; mt < 2; mt++)
        #pragma unroll
        for (int nt = 0; nt < 8; nt++)
            #pragma unroll
            for (int c = 0; c < 4; c++) acc[mt][nt][c] = 0.f;

    // prefetch slab 0
    uint4 pa0 = *(const uint4*)(Ahi + agbase);
    uint4 pa1 = *(const uint4*)(Ahi + agbase + 8);
    uint4 pl0 = *(const uint4*)(Alo + agbase);
    uint4 pl1 = *(const uint4*)(Alo + agbase + 8);
    uint4 pb0 = *(const uint4*)(Bhi + bgbase);
    uint4 pb1 = *(const uint4*)(Bhi + bgbase + 8);
    uint4 pc0 = *(const uint4*)(Blo + bgbase);
    uint4 pc1 = *(const uint4*)(Blo + bgbase + 8);

    const int NKB = HID / 32;   // 32
    for (int kb = 0; kb < NKB; kb++) {
        *(uint4*)&sAhi[row_s][kh]     = pa0;
        *(uint4*)&sAhi[row_s][kh + 8] = pa1;
        *(uint4*)&sAlo[row_s][kh]     = pl0;
        *(uint4*)&sAlo[row_s][kh + 8] = pl1;
        *(uint4*)&sBhi[row_s][kh]     = pb0;
        *(uint4*)&sBhi[row_s][kh + 8] = pb1;
        *(uint4*)&sBlo[row_s][kh]     = pc0;
        *(uint4*)&sBlo[row_s][kh + 8] = pc1;
        __syncthreads();

        if (kb + 1 < NKB) {
            const size_t ao = agbase + (size_t)(kb + 1) * 32;
            const size_t bo = bgbase + (size_t)(kb + 1) * 32;
            pa0 = *(const uint4*)(Ahi + ao);
            pa1 = *(const uint4*)(Ahi + ao + 8);
            pl0 = *(const uint4*)(Alo + ao);
            pl1 = *(const uint4*)(Alo + ao + 8);
            pb0 = *(const uint4*)(Bhi + bo);
            pb1 = *(const uint4*)(Bhi + bo + 8);
            pc0 = *(const uint4*)(Blo + bo);
            pc1 = *(const uint4*)(Blo + bo + 8);
        }

        #pragma unroll
        for (int ks = 0; ks < 2; ks++) {
            const int kk = ks * 16 + qd * 2;
            u32 fahi[2][4], falo[2][4];
            #pragma unroll
            for (int mt = 0; mt < 2; mt++) {
                const int r0 = wm * 32 + mt * 16 + grp;
                const int r1 = r0 + 8;
                fahi[mt][0] = *(const u32*)&sAhi[r0][kk];
                fahi[mt][1] = *(const u32*)&sAhi[r1][kk];
                fahi[mt][2] = *(const u32*)&sAhi[r0][kk + 8];
                fahi[mt][3] = *(const u32*)&sAhi[r1][kk + 8];
                falo[mt][0] = *(const u32*)&sAlo[r0][kk];
                falo[mt][1] = *(const u32*)&sAlo[r1][kk];
                falo[mt][2] = *(const u32*)&sAlo[r0][kk + 8];
                falo[mt][3] = *(const u32*)&sAlo[r1][kk + 8];
            }
            #pragma unroll
            for (int nt = 0; nt < 8; nt++) {
                const int bc = wn * 64 + nt * 8 + grp;
                u32 bh0 = *(const u32*)&sBhi[bc][kk];
                u32 bh1 = *(const u32*)&sBhi[bc][kk + 8];
                u32 bl0 = *(const u32*)&sBlo[bc][kk];
                u32 bl1 = *(const u32*)&sBlo[bc][kk + 8];
                #pragma unroll
                for (int mt = 0; mt < 2; mt++) {
                    mma16816(acc[mt][nt], fahi[mt], bh0, bh1);
                    mma16816(acc[mt][nt], fahi[mt], bl0, bl1);
                    mma16816(acc[mt][nt], falo[mt], bh0, bh1);
                }
            }
        }
        __syncthreads();
    }

    // epilogue: d0,d1 -> (r0, c..c+1); d2,d3 -> (r0+8, c..c+1)
    #pragma unroll
    for (int mt = 0; mt < 2; mt++) {
        #pragma unroll
        for (int nt = 0; nt < 8; nt++) {
            const int r0 = bm + wm * 32 + mt * 16 + grp;
            const int cb = bn + wn * 64 + nt * 8 + qd * 2;
            float v00 = acc[mt][nt][0], v01 = acc[mt][nt][1];
            float v10 = acc[mt][nt][2], v11 = acc[mt][nt][3];
            if (Bias) {
                float b0 = Bias[cb], b1 = Bias[cb + 1];
                v00 += b0; v01 += b1; v10 += b0; v11 += b1;
            }
            *(float2*)(Out + (size_t)r0 * HID + cb)       = make_float2(v00, v01);
            *(float2*)(Out + (size_t)(r0 + 8) * HID + cb) = make_float2(v10, v11);
        }
    }
}

// ---------------------------------------------------------------------------
// q GEMM (bit-exact FFMA2 path): BM=128, BN=256, BK=16, 8x16/thread.
// ---------------------------------------------------------------------------
#define BM 128
#define BN 256
#define BKD 16
#define TM 8
#define TN 16

struct BTile { float4 b[BKD][4][16]; };

__device__ __forceinline__
void gemm_core_128x256(const float* __restrict__ Aglob,
                       const float* __restrict__ Wglob,
                       float* __restrict__ Outp,
                       const float* __restrict__ Bias)
{
    __shared__ float As[2][BKD][BM];
    __shared__ BTile Bs[2];

    const int tid = threadIdx.x;
    const int tx  = tid & 15;
    const int ty  = tid >> 4;

    const int arow  = tid >> 1;
    const int akcol = (tid & 1) * 4;
    const int bkrow = tid >> 5;
    const int c4    = tid & 31;

    const float* Aptr = Aglob + (size_t)arow * HID + akcol;
    const float* Wp0  = Wglob + (size_t)bkrow * HID + c4 * 4;
    const float* Wp1  = Wglob + (size_t)bkrow * HID + c4 * 4 + 128;
    const float* Wp2  = Wglob + (size_t)(bkrow + 8) * HID + c4 * 4;
    const float* Wp3  = Wglob + (size_t)(bkrow + 8) * HID + c4 * 4 + 128;

    u64 acc2[TM][TN / 2];
    #pragma unroll
    for (int i = 0; i < TM; i++)
        #pragma unroll
        for (int j = 0; j < TN / 2; j++) acc2[i][j] = 0ull;

    {
        float4 a0 = *(const float4*)(Aptr);
        float4 a1 = *(const float4*)(Aptr + 8);
        float4 b0 = *(const float4*)(Wp0);
        float4 b1 = *(const float4*)(Wp1);
        float4 b2 = *(const float4*)(Wp2);
        float4 b3 = *(const float4*)(Wp3);
        As[0][akcol + 0][arow] = a0.x; As[0][akcol + 1][arow] = a0.y;
        As[0][akcol + 2][arow] = a0.z; As[0][akcol + 3][arow] = a0.w;
        As[0][akcol + 8][arow] = a1.x; As[0][akcol + 9][arow] = a1.y;
        As[0][akcol +10][arow] = a1.z; As[0][akcol +11][arow] = a1.w;
        Bs[0].b[bkrow    ][c4 >> 4      ][c4 & 15] = b0;
        Bs[0].b[bkrow    ][(c4 >> 4) + 2][c4 & 15] = b1;
        Bs[0].b[bkrow + 8][c4 >> 4      ][c4 & 15] = b2;
        Bs[0].b[bkrow + 8][(c4 >> 4) + 2][c4 & 15] = b3;
    }
    __syncthreads();

    int cur = 0;
    for (int k0 = BKD; k0 <= HID; k0 += BKD) {
        float4 a0, a1, b0, b1, b2, b3;
        const bool more = (k0 < HID);
        if (more) {
            a0 = *(const float4*)(Aptr + k0);
            a1 = *(const float4*)(Aptr + k0 + 8);
            b0 = *(const float4*)(Wp0 + (size_t)k0 * HID);
            b1 = *(const float4*)(Wp1 + (size_t)k0 * HID);
            b2 = *(const float4*)(Wp2 + (size_t)k0 * HID);
            b3 = *(const float4*)(Wp3 + (size_t)k0 * HID);
        }

        #pragma unroll
        for (int kk = 0; kk < BKD; kk++) {
            ulonglong2 q0 = *(const ulonglong2*)&Bs[cur].b[kk][0][tx];
            ulonglong2 q1 = *(const ulonglong2*)&Bs[cur].b[kk][1][tx];
            ulonglong2 q2 = *(const ulonglong2*)&Bs[cur].b[kk][2][tx];
            ulonglong2 q3 = *(const ulonglong2*)&Bs[cur].b[kk][3][tx];
            float4 av0 = *(const float4*)&As[cur][kk][ty * TM];
            float4 av1 = *(const float4*)&As[cur][kk][ty * TM + 4];
            float a[TM] = {av0.x, av0.y, av0.z, av0.w, av1.x, av1.y, av1.z, av1.w};
            #pragma unroll
            for (int i = 0; i < TM; i++) {
                u64 ap = pack_dup(a[i]);
                ffma2(acc2[i][0], ap, q0.x);
                ffma2(acc2[i][1], ap, q0.y);
                ffma2(acc2[i][2], ap, q1.x);
                ffma2(acc2[i][3], ap, q1.y);
                ffma2(acc2[i][4], ap, q2.x);
                ffma2(acc2[i][5], ap, q2.y);
                ffma2(acc2[i][6], ap, q3.x);
                ffma2(acc2[i][7], ap, q3.y);
            }
        }

        if (more) {
            const int nxt = cur ^ 1;
            As[nxt][akcol + 0][arow] = a0.x; As[nxt][akcol + 1][arow] = a0.y;
            As[nxt][akcol + 2][arow] = a0.z; As[nxt][akcol + 3][arow] = a0.w;
            As[nxt][akcol + 8][arow] = a1.x; As[nxt][akcol + 9][arow] = a1.y;
            As[nxt][akcol +10][arow] = a1.z; As[nxt][akcol +11][arow] = a1.w;
            Bs[nxt].b[bkrow    ][c4 >> 4      ][c4 & 15] = b0;
            Bs[nxt].b[bkrow    ][(c4 >> 4) + 2][c4 & 15] = b1;
            Bs[nxt].b[bkrow + 8][c4 >> 4      ][c4 & 15] = b2;
            Bs[nxt].b[bkrow + 8][(c4 >> 4) + 2][c4 & 15] = b3;
            __syncthreads();
            cur = nxt;
        }
    }

    // acc2[i][2g],acc2[i][2g+1] hold columns g*64 + 4*tx .. +3
    float bias[4][4];
    if (Bias) {
        #pragma unroll
        for (int g = 0; g < 4; g++) {
            float4 bv = *(const float4*)(Bias + g * 64 + 4 * tx);
            bias[g][0] = bv.x; bias[g][1] = bv.y; bias[g][2] = bv.z; bias[g][3] = bv.w;
        }
    }
    #pragma unroll
    for (int i = 0; i < TM; i++) {
        float* orow = Outp + (size_t)(ty * TM + i) * HID;
        #pragma unroll
        for (int g = 0; g < 4; g++) {
            float r0, r1, r2, r3;
            unpack2(acc2[i][2 * g],     r0, r1);
            unpack2(acc2[i][2 * g + 1], r2, r3);
            if (Bias) {
                r0 += bias[g][0]; r1 += bias[g][1];
                r2 += bias[g][2]; r3 += bias[g][3];
            }
            *(float4*)(orow + g * 64 + 4 * tx) = make_float4(r0, r1, r2, r3);
        }
    }
}

__global__ __launch_bounds__(256, 1)
void gemm_q_kernel(const float* __restrict__ X,
                   const float* __restrict__ Wq, const float* __restrict__ Bq) {
    const int bm = blockIdx.x * BM;
    const int bn = blockIdx.y * BN;
    gemm_core_128x256(X + (size_t)bm * HID, Wq + bn,
                      g_q + (size_t)bm * HID + bn, Bq + bn);
}

// ---------------------------------------------------------------------------
// den + scale: strict sequential d=0..63 fmaf chain (reference rounding order)
// ---------------------------------------------------------------------------
__global__ __launch_bounds__(256, 4)
void den_scale_kernel(const float* __restrict__ Z) {
    __shared__ float tile[64][65];
    __shared__ float zsh[64];
    __shared__ float inv[64];

    const int h   = blockIdx.y;
    const int r0  = blockIdx.x * 64;
    const int tid = threadIdx.x;
    const size_t base = (size_t)r0 * HID + h * 64;

    if (tid < 64) zsh[tid] = Z[h * 64 + tid];

    #pragma unroll
    for (int t = 0; t < 4; t++) {
        int idx = tid + t * 256;
        int r   = idx >> 4;
        int c4  = (idx & 15) * 4;
        float4 v = *(const float4*)(g_q + base + (size_t)r * HID + c4);
        tile[r][c4 + 0] = v.x; tile[r][c4 + 1] = v.y;
        tile[r][c4 + 2] = v.z; tile[r][c4 + 3] = v.w;
    }
    __syncthreads();

    if (tid < 64) {
        float s = 0.f;
        for (int d = 0; d < 64; d++)
            s = fmaf(tile[tid][d], zsh[d], s);
        inv[tid] = 1.f / (fabsf(s) + 1e-6f);
    }
    __syncthreads();

    #pragma unroll
    for (int t = 0; t < 4; t++) {
        int idx = tid + t * 256;
        int r   = idx >> 4;
        int c4  = (idx & 15) * 4;
        float iv = inv[r];
        float4 v;
        v.x = tile[r][c4 + 0] * iv; v.y = tile[r][c4 + 1] * iv;
        v.z = tile[r][c4 + 2] * iv; v.w = tile[r][c4 + 3] * iv;
        *(float4*)(g_q + base + (size_t)r * HID + c4) = v;
    }
}

// ---------------------------------------------------------------------------
// state update: split-S partials (deterministic), then reduce
// ---------------------------------------------------------------------------
#define TS 16

__global__ __launch_bounds__(256, 4)
void update_state_kernel() {
    __shared__ float ks[TS][64];
    __shared__ float vs[TS][64];

    const int h      = blockIdx.y;
    const int chunk  = blockIdx.x;
    const int rows   = MROWS / NCHUNK;
    const int s_base = chunk * rows;

    const int tid = threadIdx.x;
    const int tx  = tid & 15;
    const int ty  = tid >> 4;
    const int s_l = tid >> 4;
    const int c4  = (tid & 15) * 4;

    float acc[4][4];
    #pragma unroll
    for (int i = 0; i < 4; i++)
        #pragma unroll
        for (int j = 0; j < 4; j++) acc[i][j] = 0.f;
    float zacc[4] = {0.f, 0.f, 0.f, 0.f};

    const size_t colbase = (size_t)h * 64 + c4;

    for (int s0 = s_base; s0 < s_base + rows; s0 += TS) {
        *(float4*)&ks[s_l][c4] = *(const float4*)(g_k + (size_t)(s0 + s_l) * HID + colbase);
        *(float4*)&vs[s_l][c4] = *(const float4*)(g_v + (size_t)(s0 + s_l) * HID + colbase);
        __syncthreads();

        #pragma unroll
        for (int s = 0; s < TS; s++) {
            float4 af = *(const float4*)&ks[s][ty * 4];
            float4 bf = *(const float4*)&vs[s][tx * 4];
            float a[4] = {af.x, af.y, af.z, af.w};
            float b[4] = {bf.x, bf.y, bf.z, bf.w};
            #pragma unroll
            for (int i = 0; i < 4; i++)
                #pragma unroll
                for (int j = 0; j < 4; j++)
                    acc[i][j] = fmaf(a[i], b[j], acc[i][j]);
            if (tx == 0) {
                #pragma unroll
                for (int i = 0; i < 4; i++) zacc[i] += a[i];
            }
        }
        __syncthreads();
    }

    float* mp = g_Mpart + (size_t)(chunk * NH + h) * 4096;
    #pragma unroll
    for (int i = 0; i < 4; i++)
        #pragma unroll
        for (int j = 0; j < 4; j++)
            mp[(ty * 4 + i) * 64 + tx * 4 + j] = acc[i][j];
    if (tx == 0) {
        #pragma unroll
        for (int i = 0; i < 4; i++)
            g_zpart[(size_t)chunk * Z_ELEMS + h * 64 + ty * 4 + i] = zacc[i];
    }
}

__global__ void reduce_state_kernel(const float* __restrict__ M,
                                    const float* __restrict__ z,
                                    float* __restrict__ outM,
                                    float* __restrict__ outz) {
    int i = blockIdx.x * 256 + threadIdx.x;
    if (i < M_ELEMS) {
        int h = i >> 12;
        int r = i & 4095;
        float s = M[i];
        for (int c = 0; c < NCHUNK; c++)
            s += g_Mpart[(size_t)(c * NH + h) * 4096 + r];
        outM[i] = s;
    }
    if (i < Z_ELEMS) {
        float s = z[i];
        for (int c = 0; c < NCHUNK; c++)
            s += g_zpart[(size_t)c * Z_ELEMS + i];
        outz[i] = s;
    }
}

// ---------------------------------------------------------------------------
// Launch
// ---------------------------------------------------------------------------
extern "C" void kernel_launch(void* const* d_in, const int* in_sizes, int n_in,
                              void* d_out, int out_size) {
    const float* X  = (const float*)d_in[0];
    const float* M  = (const float*)d_in[1];
    const float* z  = (const float*)d_in[2];
    const float* Wq = (const float*)d_in[3];
    const float* bq = (const float*)d_in[4];
    const float* Wk = (const float*)d_in[5];
    const float* bk = (const float*)d_in[6];
    const float* Wv = (const float*)d_in[7];
    const float* bv = (const float*)d_in[8];
    const float* Wo = (const float*)d_in[9];

    float* out  = (float*)d_out;
    float* outM = out + OUT_ELEMS;
    float* outz = out + OUT_ELEMS + M_ELEMS;

    // 1. W2 = blockdiag(M) @ Wo (fp32)
    build_w2_kernel<<<dim3(16, 16), 256>>>(M, Wo);
    // 2. weight conversions (transpose + bf16 split)
    conv_w_kernel<<<dim3(32, 32), 256>>>(Wk, 0);
    conv_w_kernel<<<dim3(32, 32), 256>>>(Wv, 1);
    conv_w_kernel<<<dim3(32, 32), 256>>>((const float*)0, 2);   // g_W2
    // 3. X -> bf16 split
    split_kernel<<<OUT_ELEMS / 4 / 256, 256>>>(X);
    // 4. q projection (bit-exact FFMA2 path)
    gemm_q_kernel<<<dim3(MROWS / BM, HID / BN), 256>>>(X, Wq, bq);
    // 5. k, v projections (bf16-split mma.sync)
    mma_gemm_kernel<<<dim3(MROWS / 128, HID / 128), 256>>>(0, bk, (float*)0);
    mma_gemm_kernel<<<dim3(MROWS / 128, HID / 128), 256>>>(1, bv, (float*)0);
    // 6. den (strict order) + scale q in place
    den_scale_kernel<<<dim3(MROWS / 64, NH), 256>>>(z);
    // 7. q/den -> bf16 split
    split_kernel<<<OUT_ELEMS / 4 / 256, 256>>>((const float*)0);
    // 8. out = (q/den) @ W2 (bf16-split mma.sync)
    mma_gemm_kernel<<<dim3(MROWS / 128, HID / 128), 256>>>(2, (const float*)0, out);
    // 9. state update
    update_state_kernel<<<dim3(NCHUNK, NH), 256>>>();
    reduce_state_kernel<<<256, 256>>>(M, z, outM, outz);
}